// round 11
// baseline (speedup 1.0000x reference)
#include <cuda_runtime.h>
#include <cuda_fp16.h>
#include <math.h>

#define N_NODES_MAX 50000
#define F 64
#define NEG 0.01f
#define CAP 128
#define ASTRIDE 136   // halves per shared row: word stride 68 == 4 mod 32 banks

// ---- scratch ----
__device__ float  g_ssrc[N_NODES_MAX];
__device__ float  g_sdst[N_NODES_MAX];
__device__ int    g_cnt [N_NODES_MAX];
__device__ int2   g_ebuf[N_NODES_MAX * CAP];
__device__ __half g_AH[N_NODES_MAX * 128];   // fp16 feature rows (cols 0-63 used)
__device__ __half g_WH[64 * 128];            // fp16 copy of lin_w

// K1: node attention scores (4 threads/node) + zero cnt + fp16 feature copy
// + one-time fp16 W conversion (first 2048 global threads).
__global__ void k_scores(const float4* __restrict__ feat4,
                         const float*  __restrict__ attw,
                         const float*  __restrict__ lin_w,
                         int n)
{
    int t = blockIdx.x * blockDim.x + threadIdx.x;

    if (t < 2048) {   // convert W: 8192 floats = 2048 float4
        float4 w = __ldg((const float4*)&lin_w[t * 4]);
        __half2 h0 = __floats2half2_rn(w.x, w.y);
        __half2 h1 = __floats2half2_rn(w.z, w.w);
        uint2 u;
        u.x = *(unsigned int*)&h0;
        u.y = *(unsigned int*)&h1;
        *(uint2*)&g_WH[t * 4] = u;
    }

    int node = t >> 2;
    int p = t & 3;
    if (node >= n) return;

    float as = 0.f, ad = 0.f;
#pragma unroll
    for (int j = 0; j < 4; j++) {
        int q = p * 4 + j;
        float4 f = feat4[node * 16 + q];
        float4 wa = __ldg((const float4*)&attw[q * 4]);
        float4 wb = __ldg((const float4*)&attw[64 + q * 4]);
        as += f.x * wa.x + f.y * wa.y + f.z * wa.z + f.w * wa.w;
        ad += f.x * wb.x + f.y * wb.y + f.z * wb.z + f.w * wb.w;
        __half2 h0 = __floats2half2_rn(f.x, f.y);
        __half2 h1 = __floats2half2_rn(f.z, f.w);
        uint2 u;
        u.x = *(unsigned int*)&h0;
        u.y = *(unsigned int*)&h1;
        *(uint2*)&g_AH[node * 128 + q * 4] = u;
    }
    as += __shfl_xor_sync(0xffffffffu, as, 1);
    as += __shfl_xor_sync(0xffffffffu, as, 2);
    ad += __shfl_xor_sync(0xffffffffu, ad, 1);
    ad += __shfl_xor_sync(0xffffffffu, ad, 2);

    if (p == 0) {
        g_ssrc[node] = as;
        g_sdst[node] = ad;
        g_cnt[node]  = 0;
    }
}

// K2: per-edge exp score + bucket scatter.
__global__ void k_scatter(const int* __restrict__ src,
                          const int* __restrict__ dst,
                          int E)
{
    int e = blockIdx.x * blockDim.x + threadIdx.x;
    if (e >= E) return;
    int s = src[e], d = dst[e];
    float v = g_ssrc[s] + g_sdst[d];
    v = v > 0.f ? v : NEG * v;
    float ex = __expf(v);
    int slot = atomicAdd(&g_cnt[d], 1);
    if (slot < CAP)
        g_ebuf[(size_t)d * CAP + slot] = make_int2(s, __float_as_int(ex));
}

// ---- HMMA m16n8k16 f16 x f16 -> f32 ----
__device__ __forceinline__ void mma16816(float& c0, float& c1, float& c2, float& c3,
                                         unsigned a0, unsigned a1, unsigned a2, unsigned a3,
                                         unsigned b0, unsigned b1)
{
    asm volatile("mma.sync.aligned.m16n8k16.row.col.f32.f16.f16.f32 "
                 "{%0,%1,%2,%3}, {%4,%5,%6,%7}, {%8,%9}, {%0,%1,%2,%3};"
                 : "+f"(c0), "+f"(c1), "+f"(c2), "+f"(c3)
                 : "r"(a0), "r"(a1), "r"(a2), "r"(a3), "r"(b0), "r"(b1));
}

// K3 (fused agg + output GEMM): 1024 threads = 32 warps per block, 64 nodes.
// Agg: one node per warp per pass; bucket entries loaded COALESCED (32/LDG),
//   (src, ex) distributed via shfl; feature gather = 4B/lane full-warp row,
//   4 independent gathers in flight; acc in fp32; hm written fp16 to A tile.
// GEMM: 32 warps each compute one m16n8k16 tile of h = relu(A @ W^T + b).
__global__ void __launch_bounds__(1024) k_fused(
                      const float* __restrict__ lin_b,
                      float*       __restrict__ out,     // [n, 64]
                      int n)
{
    __shared__ __align__(16) __half W_s[64 * ASTRIDE];
    __shared__ __align__(16) __half A_s[64 * ASTRIDE];
    __shared__ float b_s[64];

    int tid = threadIdx.x;
    int base = blockIdx.x * 64;

    // stage W (fp16, 16KB): 1024 threads x 1 uint4 (8 halves)
    {
        int o = tid >> 4, c = tid & 15;
        uint4 w = *(const uint4*)&g_WH[o * 128 + c * 8];
        *(uint4*)&W_s[o * ASTRIDE + c * 8] = w;
    }
    if (tid < 64) b_s[tid] = __ldg(&lin_b[tid]);
    // stage feature half of A tile: 64 rows x 8 uint4
    if (tid < 512) {
        int r = tid >> 3, c = tid & 7;
        int node = base + r;
        if (node >= n) node = n - 1;
        uint4 v = *(const uint4*)&g_AH[(size_t)node * 128 + c * 8];
        *(uint4*)&A_s[r * ASTRIDE + c * 8] = v;
    }

    int warp = tid >> 5, lane = tid & 31;
    const unsigned* ahw = (const unsigned*)g_AH;   // 4B = 2 halves per lane

#pragma unroll
    for (int pass = 0; pass < 2; pass++) {
        int row = warp + pass * 32;
        int node = base + row;
        if (node < n) {
            int deg = g_cnt[node];
            if (deg > CAP) deg = CAP;
            const int2* eb = &g_ebuf[(size_t)node * CAP];

            float ax = 0.f, ay = 0.f;
            float dsum = 0.f;

            for (int j0 = 0; j0 < deg; j0 += 32) {
                // coalesced: 32 bucket entries in one LDG (always in-bounds:
                // j0+lane < CAP)
                int2 ent = __ldg(&eb[j0 + lane]);
                int m = deg - j0;
                if (m > 32) m = 32;

                int i = 0;
                for (; i + 4 <= m; i += 4) {
                    int s0 = __shfl_sync(0xffffffffu, ent.x, i + 0);
                    int s1 = __shfl_sync(0xffffffffu, ent.x, i + 1);
                    int s2 = __shfl_sync(0xffffffffu, ent.x, i + 2);
                    int s3 = __shfl_sync(0xffffffffu, ent.x, i + 3);
                    float x0 = __int_as_float(__shfl_sync(0xffffffffu, ent.y, i + 0));
                    float x1 = __int_as_float(__shfl_sync(0xffffffffu, ent.y, i + 1));
                    float x2 = __int_as_float(__shfl_sync(0xffffffffu, ent.y, i + 2));
                    float x3 = __int_as_float(__shfl_sync(0xffffffffu, ent.y, i + 3));
                    unsigned u0 = ahw[s0 * 64 + lane];
                    unsigned u1 = ahw[s1 * 64 + lane];
                    unsigned u2 = ahw[s2 * 64 + lane];
                    unsigned u3 = ahw[s3 * 64 + lane];
                    float2 f0 = __half22float2(*(__half2*)&u0);
                    float2 f1 = __half22float2(*(__half2*)&u1);
                    float2 f2 = __half22float2(*(__half2*)&u2);
                    float2 f3 = __half22float2(*(__half2*)&u3);
                    ax += x0 * f0.x + x1 * f1.x + x2 * f2.x + x3 * f3.x;
                    ay += x0 * f0.y + x1 * f1.y + x2 * f2.y + x3 * f3.y;
                    dsum += x0 + x1 + x2 + x3;
                }
                for (; i < m; i++) {
                    int s0 = __shfl_sync(0xffffffffu, ent.x, i);
                    float x0 = __int_as_float(__shfl_sync(0xffffffffu, ent.y, i));
                    unsigned u0 = ahw[s0 * 64 + lane];
                    float2 f0 = __half22float2(*(__half2*)&u0);
                    ax += x0 * f0.x;
                    ay += x0 * f0.y;
                    dsum += x0;
                }
            }

            float inv = dsum > 0.f ? 1.f / dsum : 0.f;
            __half2 h = __floats2half2_rn(ax * inv, ay * inv);
            *(unsigned*)&A_s[row * ASTRIDE + 64 + lane * 2] = *(unsigned*)&h;
        }
    }

    __syncthreads();

    // GEMM: warp -> (m-tile r, n-tile i)
    {
        int r = warp & 3, i = warp >> 2;
        int g = lane >> 2, j = lane & 3;
        int arow = r * 16 + g;

        float c0 = 0.f, c1 = 0.f, c2 = 0.f, c3 = 0.f;
#pragma unroll
        for (int s = 0; s < 8; s++) {
            int k0 = 16 * s;
            unsigned a0 = *(const unsigned*)&A_s[arow * ASTRIDE + k0 + 2 * j];
            unsigned a1 = *(const unsigned*)&A_s[(arow + 8) * ASTRIDE + k0 + 2 * j];
            unsigned a2 = *(const unsigned*)&A_s[arow * ASTRIDE + k0 + 8 + 2 * j];
            unsigned a3 = *(const unsigned*)&A_s[(arow + 8) * ASTRIDE + k0 + 8 + 2 * j];
            unsigned b0 = *(const unsigned*)&W_s[(8 * i + g) * ASTRIDE + k0 + 2 * j];
            unsigned b1 = *(const unsigned*)&W_s[(8 * i + g) * ASTRIDE + k0 + 8 + 2 * j];
            mma16816(c0, c1, c2, c3, a0, a1, a2, a3, b0, b1);
        }

        int c = 8 * i + 2 * j;
        float2 bb = *(const float2*)&b_s[c];
        int n0 = base + arow;
        int n1 = n0 + 8;
        if (n0 < n) {
            float2 r0;
            r0.x = fmaxf(c0 + bb.x, 0.f);
            r0.y = fmaxf(c1 + bb.y, 0.f);
            *(float2*)&out[(size_t)n0 * 64 + c] = r0;
        }
        if (n1 < n) {
            float2 r1;
            r1.x = fmaxf(c2 + bb.x, 0.f);
            r1.y = fmaxf(c3 + bb.y, 0.f);
            *(float2*)&out[(size_t)n1 * 64 + c] = r1;
        }
    }
}

extern "C" void kernel_launch(void* const* d_in, const int* in_sizes, int n_in,
                              void* d_out, int out_size)
{
    const float* feature = (const float*)d_in[0];   // [N, 64]
    const float* attn_w  = (const float*)d_in[1];   // [128, 1]
    const float* lin_w   = (const float*)d_in[2];   // [64, 128]
    const float* lin_b   = (const float*)d_in[3];   // [64]
    const int*   src     = (const int*)d_in[4];     // [E]
    const int*   dst     = (const int*)d_in[5];     // [E]

    int n = in_sizes[0] / F;
    int E = in_sizes[4];

    const float4* feat4 = (const float4*)feature;

    {   // K1: scores + cnt reset + fp16 feature & W conversion
        int threads = 256;
        long long total = (long long)n * 4;
        int blocks = (int)((total + threads - 1) / threads);
        k_scores<<<blocks, threads>>>(feat4, attn_w, lin_w, n);
    }
    {   // K2: edge scatter
        int threads = 256;
        int blocks = (E + threads - 1) / threads;
        k_scatter<<<blocks, threads>>>(src, dst, E);
    }
    {   // K3: fused aggregation + output GEMM (64 nodes / 1024-thread block)
        int blocks = (n + 63) / 64;
        k_fused<<<blocks, 1024>>>(lin_b, (float*)d_out, n);
    }
}